// round 1
// baseline (speedup 1.0000x reference)
#include <cuda_runtime.h>
#include <cuda_bf16.h>

// out[n,c,hw] = sum_k act[n,k,hw] * g[(c-k) & 255]
// where g = IDFT( 1 / DFT(delta - padded_rolled_kernel) )  (circulant inverse)

__device__ float g_dev[256];

// ---------------------------------------------------------------------------
// Prep: compute g[256] from the 27-tap ricker filter. One block, 256 threads.
// ---------------------------------------------------------------------------
__global__ void prep_kernel(const float* __restrict__ filt) {
    __shared__ float m_s[256];
    __shared__ float twc[256];
    __shared__ float tws[256];
    __shared__ float gre[256];
    __shared__ float gim[256];

    int t = threadIdx.x;

    // padded: pad_left = (256-27)/2 = 114, filt occupies [114,141)
    // rolled: kernel_vec[i] = padded[(i - 129) & 255]   (roll by 256/2+1 = 129)
    int p = (t - 129) & 255;
    float kv = (p >= 114 && p < 141) ? filt[p - 114] : 0.0f;
    m_s[t] = (t == 0 ? 1.0f : 0.0f) - kv;

    // twiddle: tw[j] = exp(-2*pi*i*j/256) = (cos, sin) of pi * (-j/128)
    float s, c;
    sincospif(-(float)t / 128.0f, &s, &c);
    twc[t] = c;
    tws[t] = s;
    __syncthreads();

    // Mhat[t] = sum_d m[d] * tw[(t*d) & 255]
    float re = 0.0f, im = 0.0f;
    for (int d = 0; d < 256; ++d) {
        int idx = (t * d) & 255;
        float md = m_s[d];
        re = fmaf(md, twc[idx], re);
        im = fmaf(md, tws[idx], im);
    }
    // Ghat = 1 / Mhat  (complex reciprocal)
    float inv = 1.0f / (re * re + im * im);
    gre[t] = re * inv;
    gim[t] = -im * inv;
    __syncthreads();

    // g[d] = (1/256) * Re{ sum_t Ghat[t] * exp(+2*pi*i*t*d/256) }
    //      = (1/256) * sum_t ( gre[t]*twc[(t*d)&255] + gim[t]*tws[(t*d)&255] )
    float g = 0.0f;
    for (int q = 0; q < 256; ++q) {
        int idx = (t * q) & 255;
        g = fmaf(gre[q], twc[idx], g);
        g = fmaf(gim[q], tws[idx], g);
    }
    g_dev[t] = g * (1.0f / 256.0f);
}

// ---------------------------------------------------------------------------
// Main GEMM: per batch n, out_n[c, hw] = sum_k T[k][c] * A_n[k][hw],
// T[k][c] = g[(c-k)&255] synthesized in SMEM (no global weight traffic).
// Tile: BM=128 (c) x BN=128 (hw) x BK=16, 256 threads, 8x8 per-thread tile
// computed with packed fma.rn.f32x2 (2 FMA/issue on the fma pipe).
// ---------------------------------------------------------------------------

__device__ __forceinline__ unsigned long long pack2(float x, float y) {
    unsigned long long r;
    asm("mov.b64 %0, {%1, %2};" : "=l"(r) : "f"(x), "f"(y));
    return r;
}

#define FMA2(d, a, b) \
    asm("fma.rn.f32x2 %0, %1, %2, %0;" : "+l"(d) : "l"(a), "l"(b))

__device__ __forceinline__ void unpack2(unsigned long long v, float& lo, float& hi) {
    asm("mov.b64 {%0, %1}, %2;" : "=f"(lo), "=f"(hi) : "l"(v));
}

__global__ __launch_bounds__(256, 2)
void toeplitz_gemm_kernel(const float* __restrict__ act, float* __restrict__ out) {
    __shared__ float g_s[256];
    __shared__ __align__(16) float Bs[16][128];  // act tile   [k][hw]
    __shared__ __align__(16) float Ts[16][128];  // weight tile [k][c]

    const int t  = threadIdx.x;
    const int tx = t & 15;   // hw direction
    const int ty = t >> 4;   // c  direction

    const int hw0 = blockIdx.x * 128;
    const int c0  = blockIdx.y * 128;
    const int n   = blockIdx.z;

    const float* actn = act + (size_t)n * 256 * 4096;

    g_s[t] = g_dev[t];

    unsigned long long acc[8][4];
#pragma unroll
    for (int i = 0; i < 8; ++i)
#pragma unroll
        for (int j = 0; j < 4; ++j) acc[i][j] = 0ULL;

    for (int k0 = 0; k0 < 256; k0 += 16) {
        __syncthreads();  // prev-iter reads done (and g_s visible on iter 0)

        // Load Bs: 16x128 floats = 512 float4, 2 per thread. Coalesced along hw.
#pragma unroll
        for (int l = 0; l < 2; ++l) {
            int f4  = t + l * 256;
            int row = f4 >> 5;
            int col = (f4 & 31) << 2;
            *(float4*)&Bs[row][col] =
                *(const float4*)&actn[(size_t)(k0 + row) * 4096 + hw0 + col];
        }
        // Synthesize Ts from g (circulant): Ts[kk][cc] = g[(c0+cc - k0-kk) & 255]
#pragma unroll
        for (int l = 0; l < 8; ++l) {
            int i  = t + l * 256;
            int kk = i >> 7;
            int cc = i & 127;
            Ts[kk][cc] = g_s[(c0 + cc - k0 - kk) & 255];
        }
        __syncthreads();

#pragma unroll
        for (int kk = 0; kk < 16; ++kk) {
            float4 a0 = *(const float4*)&Ts[kk][ty * 8];
            float4 a1 = *(const float4*)&Ts[kk][ty * 8 + 4];
            ulonglong2 b0 = *(const ulonglong2*)&Bs[kk][tx * 8];
            ulonglong2 b1 = *(const ulonglong2*)&Bs[kk][tx * 8 + 4];

            unsigned long long av[8];
            av[0] = pack2(a0.x, a0.x);
            av[1] = pack2(a0.y, a0.y);
            av[2] = pack2(a0.z, a0.z);
            av[3] = pack2(a0.w, a0.w);
            av[4] = pack2(a1.x, a1.x);
            av[5] = pack2(a1.y, a1.y);
            av[6] = pack2(a1.z, a1.z);
            av[7] = pack2(a1.w, a1.w);

#pragma unroll
            for (int i = 0; i < 8; ++i) {
                FMA2(acc[i][0], av[i], b0.x);
                FMA2(acc[i][1], av[i], b0.y);
                FMA2(acc[i][2], av[i], b1.x);
                FMA2(acc[i][3], av[i], b1.y);
            }
        }
    }

    float* outn = out + (size_t)n * 256 * 4096;
#pragma unroll
    for (int i = 0; i < 8; ++i) {
        float r[8];
#pragma unroll
        for (int j = 0; j < 4; ++j) unpack2(acc[i][j], r[2 * j], r[2 * j + 1]);
        float4 v0 = make_float4(r[0], r[1], r[2], r[3]);
        float4 v1 = make_float4(r[4], r[5], r[6], r[7]);
        int c = c0 + ty * 8 + i;
        *(float4*)&outn[(size_t)c * 4096 + hw0 + tx * 8]     = v0;
        *(float4*)&outn[(size_t)c * 4096 + hw0 + tx * 8 + 4] = v1;
    }
}

// ---------------------------------------------------------------------------
extern "C" void kernel_launch(void* const* d_in, const int* in_sizes, int n_in,
                              void* d_out, int out_size) {
    const float* act;
    const float* filt;
    if (n_in >= 2 && in_sizes[0] == 27) {
        filt = (const float*)d_in[0];
        act  = (const float*)d_in[1];
    } else {
        act  = (const float*)d_in[0];
        filt = (const float*)d_in[1];
    }

    prep_kernel<<<1, 256>>>(filt);

    dim3 grid(4096 / 128, 256 / 128, 32);  // (32, 2, 32)
    toeplitz_gemm_kernel<<<grid, 256>>>(act, (float*)d_out);
}

// round 3
// speedup vs baseline: 1.9663x; 1.9663x over previous
#include <cuda_runtime.h>
#include <cuda_bf16.h>
#include <cstdint>

// ============================================================================
// out[n,c,hw] = sum_k g[(c-k)&255] * act[n,k,hw]   (circulant inverse GEMM)
// mma.sync m16n8k16 bf16 (base PTX, valid on compute_103), 3-term hi/lo split.
// CTA: 256c x 64hw, 512 threads (16 warps: 4 M-groups x 4 N-groups).
// ============================================================================

__device__ __nv_bfloat16 ghi_d[256];
__device__ __nv_bfloat16 glo_d[256];

// ---------------------------------------------------------------------------
// Prep: g = IDFT(1/DFT(delta - padded_rolled_ricker)), bf16 hi/lo split.
// ---------------------------------------------------------------------------
__global__ void prep_kernel(const float* __restrict__ filt) {
    __shared__ float m_s[256];
    __shared__ float twc[256];
    __shared__ float tws[256];
    __shared__ float gre[256];
    __shared__ float gim[256];

    int t = threadIdx.x;
    // pad_left = (256-27)/2 = 114 ; roll by 256/2+1 = 129
    int p = (t - 129) & 255;
    float kv = (p >= 114 && p < 141) ? filt[p - 114] : 0.0f;
    m_s[t] = (t == 0 ? 1.0f : 0.0f) - kv;

    float s, c;
    sincospif(-(float)t / 128.0f, &s, &c);
    twc[t] = c;
    tws[t] = s;
    __syncthreads();

    float re = 0.0f, im = 0.0f;
    for (int d = 0; d < 256; ++d) {
        int idx = (t * d) & 255;
        re = fmaf(m_s[d], twc[idx], re);
        im = fmaf(m_s[d], tws[idx], im);
    }
    float inv = 1.0f / (re * re + im * im);
    gre[t] = re * inv;
    gim[t] = -im * inv;
    __syncthreads();

    float g = 0.0f;
    for (int q = 0; q < 256; ++q) {
        int idx = (t * q) & 255;
        g = fmaf(gre[q], twc[idx], g);
        g = fmaf(gim[q], tws[idx], g);
    }
    g *= (1.0f / 256.0f);

    __nv_bfloat16 hi = __float2bfloat16_rn(g);
    __nv_bfloat16 lo = __float2bfloat16_rn(g - __bfloat162float(hi));
    ghi_d[t] = hi;
    glo_d[t] = lo;
}

// ---------------------------------------------------------------------------
// PTX helpers (base-PTX only: ldmatrix + mma.sync, sm_80-era features)
// ---------------------------------------------------------------------------
__device__ __forceinline__ uint32_t smem_u32(const void* p) {
    uint32_t a;
    asm("{ .reg .u64 t; cvta.to.shared.u64 t, %1; cvt.u32.u64 %0, t; }"
        : "=r"(a) : "l"(p));
    return a;
}
__device__ __forceinline__ void ldsm_x4(uint32_t* r, uint32_t addr) {
    asm volatile("ldmatrix.sync.aligned.m8n8.x4.shared.b16 {%0,%1,%2,%3}, [%4];"
                 : "=r"(r[0]), "=r"(r[1]), "=r"(r[2]), "=r"(r[3]) : "r"(addr));
}
__device__ __forceinline__ void ldsm_x4_t(uint32_t* r, uint32_t addr) {
    asm volatile("ldmatrix.sync.aligned.m8n8.x4.trans.shared.b16 {%0,%1,%2,%3}, [%4];"
                 : "=r"(r[0]), "=r"(r[1]), "=r"(r[2]), "=r"(r[3]) : "r"(addr));
}
__device__ __forceinline__ void mma16816(float* d, const uint32_t* a,
                                         const uint32_t* b) {
    asm volatile(
        "mma.sync.aligned.m16n8k16.row.col.f32.bf16.bf16.f32 "
        "{%0,%1,%2,%3},{%4,%5,%6,%7},{%8,%9},{%0,%1,%2,%3};"
        : "+f"(d[0]), "+f"(d[1]), "+f"(d[2]), "+f"(d[3])
        : "r"(a[0]), "r"(a[1]), "r"(a[2]), "r"(a[3]), "r"(b[0]), "r"(b[1]));
}

// SMEM layout (padded pitches -> conflict-free ldmatrix)
static constexpr uint32_t A_PITCH = 80;    // 32 bf16 (64B) + 16B pad
static constexpr uint32_t B_PITCH = 144;   // 64 bf16 (128B) + 16B pad
static constexpr uint32_t OFF_AH  = 0;                  // 256*80 = 20480
static constexpr uint32_t OFF_AL  = 20480;              // 20480
static constexpr uint32_t OFF_B   = 40960;              // 4 bufs * 32*144
static constexpr uint32_t B_BUF   = 32 * B_PITCH;       // 4608
static constexpr uint32_t SMEM_BYTES = 40960 + 4 * B_BUF;  // 59392

__global__ __launch_bounds__(512, 1)
void mma_toeplitz_kernel(const float* __restrict__ act, float* __restrict__ out) {
    extern __shared__ __align__(128) char smem[];
    const uint32_t sb = smem_u32(smem);
    const int tid = threadIdx.x;
    const int lid = tid & 31;
    const int wid = tid >> 5;
    const int warp_m = wid >> 2;   // 0..3 -> 64 c each
    const int warp_n = wid & 3;    // 0..3 -> 16 hw each
    const int hw0 = blockIdx.x * 64;
    const int n   = blockIdx.y;

    const float* actn = act + (size_t)n * (256 * 4096);
    float*       outn = out + (size_t)n * (256 * 4096);

    // Synthesize circulant A tables: Aext[s][kk] = g[(s-kk)&255]
    for (int i = tid; i < 256 * 32; i += 512) {
        int s = i >> 5, kk = i & 31;
        int gi = (s - kk) & 255;
        *(__nv_bfloat16*)(smem + OFF_AH + s * A_PITCH + kk * 2) = ghi_d[gi];
        *(__nv_bfloat16*)(smem + OFF_AL + s * A_PITCH + kk * 2) = glo_d[gi];
    }

    float acc[4][2][4] = {};

    const int ld_k = tid >> 4;          // 0..31
    const int ld_c = (tid & 15) * 4;    // 0..60
    float4 v = *(const float4*)&actn[(size_t)ld_k * 4096 + hw0 + ld_c];

    for (int j = 0; j < 8; ++j) {
        const uint32_t bh_off = OFF_B + ((j & 1) * 2 + 0) * B_BUF;
        const uint32_t bl_off = OFF_B + ((j & 1) * 2 + 1) * B_BUF;

        __syncthreads();   // prior compute done reading this buffer (and A synth on j=0)

        // convert fp32 -> bf16 hi/lo, store [k][n] (n contiguous)
        {
            __nv_bfloat16 h0 = __float2bfloat16_rn(v.x);
            __nv_bfloat16 h1 = __float2bfloat16_rn(v.y);
            __nv_bfloat16 h2 = __float2bfloat16_rn(v.z);
            __nv_bfloat16 h3 = __float2bfloat16_rn(v.w);
            __nv_bfloat16 e0 = __float2bfloat16_rn(v.x - __bfloat162float(h0));
            __nv_bfloat16 e1 = __float2bfloat16_rn(v.y - __bfloat162float(h1));
            __nv_bfloat16 e2 = __float2bfloat16_rn(v.z - __bfloat162float(h2));
            __nv_bfloat16 e3 = __float2bfloat16_rn(v.w - __bfloat162float(h3));
            __nv_bfloat162 hA = __halves2bfloat162(h0, h1);
            __nv_bfloat162 hB = __halves2bfloat162(h2, h3);
            __nv_bfloat162 lA = __halves2bfloat162(e0, e1);
            __nv_bfloat162 lB = __halves2bfloat162(e2, e3);
            uint32_t off = (uint32_t)ld_k * B_PITCH + (uint32_t)(tid & 15) * 8;
            *(uint2*)(smem + bh_off + off) =
                make_uint2(*(uint32_t*)&hA, *(uint32_t*)&hB);
            *(uint2*)(smem + bl_off + off) =
                make_uint2(*(uint32_t*)&lA, *(uint32_t*)&lB);
        }
        __syncthreads();

        if (j < 7)
            v = *(const float4*)&actn[(size_t)((j + 1) * 32 + ld_k) * 4096 + hw0 + ld_c];

        const uint32_t bh = sb + bh_off;
        const uint32_t bl = sb + bl_off;
#pragma unroll
        for (int step = 0; step < 2; ++step) {
            // B fragments: lanes 0-15 -> k rows, lanes 16-31 -> n+8
            uint32_t brow = (uint32_t)(step * 16 + (lid & 15));
            uint32_t bcol = (uint32_t)(warp_n * 16 + ((lid >> 4) << 3));
            uint32_t Bh[4], Bl[4];
            ldsm_x4_t(Bh, bh + brow * B_PITCH + bcol * 2);
            ldsm_x4_t(Bl, bl + brow * B_PITCH + bcol * 2);
#pragma unroll
            for (int mt = 0; mt < 4; ++mt) {
                int sbase = ((warp_m * 64 + mt * 16) - j * 32) & 255;
                uint32_t arow = (uint32_t)(sbase + (lid & 15));
                uint32_t acol = (uint32_t)(step * 32 + ((lid >> 4) << 4));  // bytes
                uint32_t Ah[4], Al[4];
                ldsm_x4(Ah, sb + OFF_AH + arow * A_PITCH + acol);
                ldsm_x4(Al, sb + OFF_AL + arow * A_PITCH + acol);
                mma16816(acc[mt][0], Ah, Bh);
                mma16816(acc[mt][1], Ah, Bh + 2);
                mma16816(acc[mt][0], Ah, Bl);
                mma16816(acc[mt][1], Ah, Bl + 2);
                mma16816(acc[mt][0], Al, Bh);
                mma16816(acc[mt][1], Al, Bh + 2);
            }
        }
    }

    // Epilogue: direct stores; quads of lanes cover 32B sectors contiguously
#pragma unroll
    for (int mt = 0; mt < 4; ++mt) {
        int c = warp_m * 64 + mt * 16 + (lid >> 2);
#pragma unroll
        for (int nt = 0; nt < 2; ++nt) {
            int col = hw0 + warp_n * 16 + nt * 8 + (lid & 3) * 2;
            *(float2*)&outn[(size_t)c * 4096 + col] =
                make_float2(acc[mt][nt][0], acc[mt][nt][1]);
            *(float2*)&outn[(size_t)(c + 8) * 4096 + col] =
                make_float2(acc[mt][nt][2], acc[mt][nt][3]);
        }
    }
}

// ---------------------------------------------------------------------------
extern "C" void kernel_launch(void* const* d_in, const int* in_sizes, int n_in,
                              void* d_out, int out_size) {
    const float* act;
    const float* filt;
    if (n_in >= 2 && in_sizes[0] == 27) {
        filt = (const float*)d_in[0];
        act  = (const float*)d_in[1];
    } else {
        act  = (const float*)d_in[0];
        filt = (const float*)d_in[1];
    }

    cudaFuncSetAttribute(mma_toeplitz_kernel,
                         cudaFuncAttributeMaxDynamicSharedMemorySize, SMEM_BYTES);

    prep_kernel<<<1, 256>>>(filt);

    dim3 grid(4096 / 64, 32);   // (64, 32) = 2048 CTAs
    mma_toeplitz_kernel<<<grid, 512, SMEM_BYTES>>>(act, (float*)d_out);
}

// round 4
// speedup vs baseline: 2.3900x; 1.2155x over previous
#include <cuda_runtime.h>
#include <cuda_bf16.h>
#include <cstdint>

// ============================================================================
// out[n,c,hw] = sum_k g[(c-k)&255] * act[n,k,hw]   (circulant inverse GEMM)
// mma.sync m16n8k16 bf16, 3-term hi/lo split (A_hi*B_hi + A_hi*B_lo + A_lo*B_hi).
// CTA: 256c x 32hw, 256 threads (8 warps = 4 M x 2 N), 2 CTAs/SM for overlap.
// ============================================================================

__device__ __align__(16) __nv_bfloat16 aext_hi_g[256 * 32];
__device__ __align__(16) __nv_bfloat16 aext_lo_g[256 * 32];

// ---------------------------------------------------------------------------
// Prep: g = IDFT(1/DFT(delta - padded_rolled_ricker)); circulant table hi/lo.
// ---------------------------------------------------------------------------
__global__ void prep_kernel(const float* __restrict__ filt) {
    __shared__ float m_s[256];
    __shared__ float twc[256];
    __shared__ float tws[256];
    __shared__ float gre[256];
    __shared__ float gim[256];
    __shared__ float g_s[256];

    int t = threadIdx.x;
    // pad_left = (256-27)/2 = 114 ; roll by 256/2+1 = 129
    int p = (t - 129) & 255;
    float kv = (p >= 114 && p < 141) ? filt[p - 114] : 0.0f;
    m_s[t] = (t == 0 ? 1.0f : 0.0f) - kv;

    float s, c;
    sincospif(-(float)t / 128.0f, &s, &c);
    twc[t] = c;
    tws[t] = s;
    __syncthreads();

    float re = 0.0f, im = 0.0f;
    for (int d = 0; d < 256; ++d) {
        int idx = (t * d) & 255;
        re = fmaf(m_s[d], twc[idx], re);
        im = fmaf(m_s[d], tws[idx], im);
    }
    float inv = 1.0f / (re * re + im * im);
    gre[t] = re * inv;
    gim[t] = -im * inv;
    __syncthreads();

    float g = 0.0f;
    for (int q = 0; q < 256; ++q) {
        int idx = (t * q) & 255;
        g = fmaf(gre[q], twc[idx], g);
        g = fmaf(gim[q], tws[idx], g);
    }
    g_s[t] = g * (1.0f / 256.0f);
    __syncthreads();

    // Aext[s][kk] = g[(s-kk)&255]
    for (int kk = 0; kk < 32; ++kk) {
        float v = g_s[(t - kk) & 255];
        __nv_bfloat16 hi = __float2bfloat16_rn(v);
        __nv_bfloat16 lo = __float2bfloat16_rn(v - __bfloat162float(hi));
        aext_hi_g[t * 32 + kk] = hi;
        aext_lo_g[t * 32 + kk] = lo;
    }
}

// ---------------------------------------------------------------------------
// PTX helpers (base PTX only)
// ---------------------------------------------------------------------------
__device__ __forceinline__ uint32_t smem_u32(const void* p) {
    uint32_t a;
    asm("{ .reg .u64 t; cvta.to.shared.u64 t, %1; cvt.u32.u64 %0, t; }"
        : "=r"(a) : "l"(p));
    return a;
}
__device__ __forceinline__ void ldsm_x4(uint32_t* r, uint32_t addr) {
    asm volatile("ldmatrix.sync.aligned.m8n8.x4.shared.b16 {%0,%1,%2,%3}, [%4];"
                 : "=r"(r[0]), "=r"(r[1]), "=r"(r[2]), "=r"(r[3]) : "r"(addr));
}
__device__ __forceinline__ void ldsm_x4_t(uint32_t* r, uint32_t addr) {
    asm volatile("ldmatrix.sync.aligned.m8n8.x4.trans.shared.b16 {%0,%1,%2,%3}, [%4];"
                 : "=r"(r[0]), "=r"(r[1]), "=r"(r[2]), "=r"(r[3]) : "r"(addr));
}
__device__ __forceinline__ void mma16816(float* d, const uint32_t* a,
                                         const uint32_t* b) {
    asm volatile(
        "mma.sync.aligned.m16n8k16.row.col.f32.bf16.bf16.f32 "
        "{%0,%1,%2,%3},{%4,%5,%6,%7},{%8,%9},{%0,%1,%2,%3};"
        : "+f"(d[0]), "+f"(d[1]), "+f"(d[2]), "+f"(d[3])
        : "r"(a[0]), "r"(a[1]), "r"(a[2]), "r"(a[3]), "r"(b[0]), "r"(b[1]));
}

// SMEM layout: pitch 80 => ldmatrix conflict-free (20r mod 32 covers all banks)
static constexpr uint32_t A_PITCH = 80;   // 32 bf16 (64B) + 16B pad
static constexpr uint32_t B_PITCH = 80;   // 32 bf16 (64B) + 16B pad
static constexpr uint32_t OFF_AH  = 0;                 // 256*80 = 20480
static constexpr uint32_t OFF_AL  = 20480;
static constexpr uint32_t OFF_B   = 40960;
static constexpr uint32_t B_BUF   = 32 * B_PITCH;      // 2560
static constexpr uint32_t SMEM_BYTES = 40960 + 4 * B_BUF;  // 51200

__device__ __forceinline__ void convert_sts(char* smem, uint32_t bh_off,
                                            uint32_t bl_off, float4 v,
                                            uint32_t off) {
    __nv_bfloat16 h0 = __float2bfloat16_rn(v.x);
    __nv_bfloat16 h1 = __float2bfloat16_rn(v.y);
    __nv_bfloat16 h2 = __float2bfloat16_rn(v.z);
    __nv_bfloat16 h3 = __float2bfloat16_rn(v.w);
    __nv_bfloat16 e0 = __float2bfloat16_rn(v.x - __bfloat162float(h0));
    __nv_bfloat16 e1 = __float2bfloat16_rn(v.y - __bfloat162float(h1));
    __nv_bfloat16 e2 = __float2bfloat16_rn(v.z - __bfloat162float(h2));
    __nv_bfloat16 e3 = __float2bfloat16_rn(v.w - __bfloat162float(h3));
    __nv_bfloat162 hA = __halves2bfloat162(h0, h1);
    __nv_bfloat162 hB = __halves2bfloat162(h2, h3);
    __nv_bfloat162 lA = __halves2bfloat162(e0, e1);
    __nv_bfloat162 lB = __halves2bfloat162(e2, e3);
    *(uint2*)(smem + bh_off + off) = make_uint2(*(uint32_t*)&hA, *(uint32_t*)&hB);
    *(uint2*)(smem + bl_off + off) = make_uint2(*(uint32_t*)&lA, *(uint32_t*)&lB);
}

__global__ __launch_bounds__(256, 2)
void mma_toeplitz_kernel(const float* __restrict__ act, float* __restrict__ out) {
    extern __shared__ __align__(128) char smem[];
    const uint32_t sb = smem_u32(smem);
    const int tid = threadIdx.x;
    const int lid = tid & 31;
    const int wid = tid >> 5;
    const int warp_m = wid >> 1;   // 0..3 -> 64 c each
    const int warp_n = wid & 1;    // 0..1 -> 16 hw each
    const int hw0 = blockIdx.x * 32;
    const int n   = blockIdx.y;

    const float* actn = act + (size_t)n * (256 * 4096);
    float*       outn = out + (size_t)n * (256 * 4096);

    // Copy circulant A tables gmem -> smem (row 64B -> pitch 80)
    {
        const float4* srch = (const float4*)aext_hi_g;
        const float4* srcl = (const float4*)aext_lo_g;
#pragma unroll
        for (int l = 0; l < 4; ++l) {
            int i = tid + l * 256;            // 16B chunk, 0..1023
            uint32_t dst = (uint32_t)(i >> 2) * A_PITCH + (uint32_t)(i & 3) * 16;
            *(float4*)(smem + OFF_AH + dst) = srch[i];
            *(float4*)(smem + OFF_AL + dst) = srcl[i];
        }
    }

    float acc[4][2][4] = {};

    const int ld_k  = tid >> 3;         // 0..31
    const int ld_c  = (tid & 7) * 4;    // 0..28
    const uint32_t sts_off = (uint32_t)ld_k * B_PITCH + (uint32_t)(tid & 7) * 8;

    // Preload + stage chunk 0
    float4 v = *(const float4*)&actn[(size_t)ld_k * 4096 + hw0 + ld_c];
    convert_sts(smem, OFF_B, OFF_B + B_BUF, v, sts_off);

    for (int j = 0; j < 8; ++j) {
        __syncthreads();  // STS(j) visible; all warps done compute(j-1)

        if (j < 7)
            v = *(const float4*)&actn[(size_t)((j + 1) * 32 + ld_k) * 4096 + hw0 + ld_c];

        const uint32_t bh = sb + OFF_B + ((j & 1) * 2 + 0) * B_BUF;
        const uint32_t bl = sb + OFF_B + ((j & 1) * 2 + 1) * B_BUF;
#pragma unroll
        for (int step = 0; step < 2; ++step) {
            uint32_t brow = (uint32_t)(step * 16 + (lid & 15));
            uint32_t bcol = (uint32_t)(warp_n * 16 + ((lid >> 4) << 3));
            uint32_t Bh[4], Bl[4];
            ldsm_x4_t(Bh, bh + brow * B_PITCH + bcol * 2);
            ldsm_x4_t(Bl, bl + brow * B_PITCH + bcol * 2);
#pragma unroll
            for (int mt = 0; mt < 4; ++mt) {
                int sbase = ((warp_m * 64 + mt * 16) - j * 32) & 255;
                uint32_t arow = (uint32_t)(sbase + (lid & 15));
                uint32_t acol = (uint32_t)(step * 32 + ((lid >> 4) << 4));  // bytes
                uint32_t Ah[4], Al[4];
                ldsm_x4(Ah, sb + OFF_AH + arow * A_PITCH + acol);
                ldsm_x4(Al, sb + OFF_AL + arow * A_PITCH + acol);
                mma16816(acc[mt][0], Ah, Bh);
                mma16816(acc[mt][1], Ah, Bh + 2);
                mma16816(acc[mt][0], Ah, Bl);
                mma16816(acc[mt][1], Ah, Bl + 2);
                mma16816(acc[mt][0], Al, Bh);
                mma16816(acc[mt][1], Al, Bh + 2);
            }
        }

        if (j < 7) {
            uint32_t nb = ((j + 1) & 1) * 2;
            convert_sts(smem, OFF_B + nb * B_BUF, OFF_B + (nb + 1) * B_BUF,
                        v, sts_off);
        }
    }

    // Epilogue: direct stores (lane quads cover 32B sectors)
#pragma unroll
    for (int mt = 0; mt < 4; ++mt) {
        int c = warp_m * 64 + mt * 16 + (lid >> 2);
#pragma unroll
        for (int nt = 0; nt < 2; ++nt) {
            int col = hw0 + warp_n * 16 + nt * 8 + (lid & 3) * 2;
            *(float2*)&outn[(size_t)c * 4096 + col] =
                make_float2(acc[mt][nt][0], acc[mt][nt][1]);
            *(float2*)&outn[(size_t)(c + 8) * 4096 + col] =
                make_float2(acc[mt][nt][2], acc[mt][nt][3]);
        }
    }
}

// ---------------------------------------------------------------------------
extern "C" void kernel_launch(void* const* d_in, const int* in_sizes, int n_in,
                              void* d_out, int out_size) {
    const float* act;
    const float* filt;
    if (n_in >= 2 && in_sizes[0] == 27) {
        filt = (const float*)d_in[0];
        act  = (const float*)d_in[1];
    } else {
        act  = (const float*)d_in[0];
        filt = (const float*)d_in[1];
    }

    cudaFuncSetAttribute(mma_toeplitz_kernel,
                         cudaFuncAttributeMaxDynamicSharedMemorySize, SMEM_BYTES);

    prep_kernel<<<1, 256>>>(filt);

    dim3 grid(4096 / 32, 32);   // (128, 32) = 4096 CTAs
    mma_toeplitz_kernel<<<grid, 256, SMEM_BYTES>>>(act, (float*)d_out);
}

// round 5
// speedup vs baseline: 4.4612x; 1.8666x over previous
#include <cuda_runtime.h>
#include <cuda_fp16.h>
#include <cstdint>

// ============================================================================
// out[n,c,hw] = sum_k g[(c-k)&255] * act[n,k,hw]   (circulant inverse GEMM)
// Single-pass fp16 mma.sync m16n8k16 (fp32 accum). Error ~2^-11 << 1e-3 gate.
// CTA: 256c x 64hw, 256 threads (8 warps = 4 M x 2 N), 2 CTAs/SM.
// ============================================================================

__device__ __align__(16) __half aext_g[256 * 32];

// ---------------------------------------------------------------------------
// Prep: g = IDFT(1/DFT(delta - padded_rolled_ricker)); circulant fp16 table.
// ---------------------------------------------------------------------------
__global__ void prep_kernel(const float* __restrict__ filt) {
    __shared__ float m_s[256];
    __shared__ float twc[256];
    __shared__ float tws[256];
    __shared__ float gre[256];
    __shared__ float gim[256];
    __shared__ float g_s[256];

    int t = threadIdx.x;
    // pad_left = (256-27)/2 = 114 ; roll by 256/2+1 = 129
    int p = (t - 129) & 255;
    float kv = (p >= 114 && p < 141) ? filt[p - 114] : 0.0f;
    m_s[t] = (t == 0 ? 1.0f : 0.0f) - kv;

    float s, c;
    sincospif(-(float)t / 128.0f, &s, &c);
    twc[t] = c;
    tws[t] = s;
    __syncthreads();

    float re = 0.0f, im = 0.0f;
    for (int d = 0; d < 256; ++d) {
        int idx = (t * d) & 255;
        re = fmaf(m_s[d], twc[idx], re);
        im = fmaf(m_s[d], tws[idx], im);
    }
    float inv = 1.0f / (re * re + im * im);
    gre[t] = re * inv;
    gim[t] = -im * inv;
    __syncthreads();

    float g = 0.0f;
    for (int q = 0; q < 256; ++q) {
        int idx = (t * q) & 255;
        g = fmaf(gre[q], twc[idx], g);
        g = fmaf(gim[q], tws[idx], g);
    }
    g_s[t] = g * (1.0f / 256.0f);
    __syncthreads();

    // Aext[s][kk] = g[(s-kk)&255]
    for (int kk = 0; kk < 32; ++kk)
        aext_g[t * 32 + kk] = __float2half_rn(g_s[(t - kk) & 255]);
}

// ---------------------------------------------------------------------------
// PTX helpers (base PTX only)
// ---------------------------------------------------------------------------
__device__ __forceinline__ uint32_t smem_u32(const void* p) {
    uint32_t a;
    asm("{ .reg .u64 t; cvta.to.shared.u64 t, %1; cvt.u32.u64 %0, t; }"
        : "=r"(a) : "l"(p));
    return a;
}
__device__ __forceinline__ void ldsm_x4(uint32_t* r, uint32_t addr) {
    asm volatile("ldmatrix.sync.aligned.m8n8.x4.shared.b16 {%0,%1,%2,%3}, [%4];"
                 : "=r"(r[0]), "=r"(r[1]), "=r"(r[2]), "=r"(r[3]) : "r"(addr));
}
__device__ __forceinline__ void ldsm_x4_t(uint32_t* r, uint32_t addr) {
    asm volatile("ldmatrix.sync.aligned.m8n8.x4.trans.shared.b16 {%0,%1,%2,%3}, [%4];"
                 : "=r"(r[0]), "=r"(r[1]), "=r"(r[2]), "=r"(r[3]) : "r"(addr));
}
__device__ __forceinline__ void mma16816(float* d, const uint32_t* a,
                                         const uint32_t* b) {
    asm volatile(
        "mma.sync.aligned.m16n8k16.row.col.f32.f16.f16.f32 "
        "{%0,%1,%2,%3},{%4,%5,%6,%7},{%8,%9},{%0,%1,%2,%3};"
        : "+f"(d[0]), "+f"(d[1]), "+f"(d[2]), "+f"(d[3])
        : "r"(a[0]), "r"(a[1]), "r"(a[2]), "r"(a[3]), "r"(b[0]), "r"(b[1]));
}

// SMEM layout
static constexpr uint32_t A_PITCH = 80;    // 32 fp16 (64B) + 16B pad
static constexpr uint32_t B_PITCH = 144;   // 64 fp16 (128B) + 16B pad
static constexpr uint32_t OFF_A   = 0;                 // 256*80 = 20480
static constexpr uint32_t OFF_B   = 20480;
static constexpr uint32_t B_BUF   = 32 * B_PITCH;      // 4608
static constexpr uint32_t SMEM_BYTES = 20480 + 2 * B_BUF;  // 29696

__device__ __forceinline__ void sts_h(char* smem, uint32_t off, float4 v) {
    __half2 a = __floats2half2_rn(v.x, v.y);
    __half2 b = __floats2half2_rn(v.z, v.w);
    *(uint2*)(smem + off) = make_uint2(*(uint32_t*)&a, *(uint32_t*)&b);
}

__global__ __launch_bounds__(256, 2)
void mma_toeplitz_kernel(const float* __restrict__ act, float* __restrict__ out) {
    extern __shared__ __align__(128) char smem[];
    const uint32_t sb = smem_u32(smem);
    const int tid = threadIdx.x;
    const int lid = tid & 31;
    const int wid = tid >> 5;
    const int warp_m = wid >> 1;   // 0..3 -> 64 c each
    const int warp_n = wid & 1;    // 0..1 -> 32 hw each
    const int hw0 = blockIdx.x * 64;
    const int n   = blockIdx.y;

    const float* actn = act + (size_t)n * (256 * 4096);
    float*       outn = out + (size_t)n * (256 * 4096);

    // Copy circulant A table gmem -> smem (64B rows -> pitch 80)
    {
        const float4* src = (const float4*)aext_g;
#pragma unroll
        for (int l = 0; l < 4; ++l) {
            int i = tid + l * 256;            // 16B chunk, 0..1023
            uint32_t dst = (uint32_t)(i >> 2) * A_PITCH + (uint32_t)(i & 3) * 16;
            *(float4*)(smem + OFF_A + dst) = src[i];
        }
    }

    float acc[4][4][4] = {};

    const int ld_k = tid >> 3;          // 0..31
    const int ld_c = (tid & 7) * 4;     // 0..28
    const uint32_t so = (uint32_t)ld_k * B_PITCH + (uint32_t)(tid & 7) * 8;

    // Prologue: chunk 0 staged, chunk 1 in flight
    float4 va = *(const float4*)&actn[(size_t)ld_k * 4096 + hw0 + ld_c];
    float4 vb = *(const float4*)&actn[(size_t)ld_k * 4096 + hw0 + ld_c + 32];
    sts_h(smem, OFF_B + so, va);
    sts_h(smem, OFF_B + so + 64, vb);
    float4 vAa = *(const float4*)&actn[(size_t)(32 + ld_k) * 4096 + hw0 + ld_c];
    float4 vAb = *(const float4*)&actn[(size_t)(32 + ld_k) * 4096 + hw0 + ld_c + 32];

    for (int j = 0; j < 8; ++j) {
        __syncthreads();  // STS(j) visible; all warps done compute(j-1)

        float4 vBa, vBb;
        if (j < 6) {
            vBa = *(const float4*)&actn[(size_t)((j + 2) * 32 + ld_k) * 4096 + hw0 + ld_c];
            vBb = *(const float4*)&actn[(size_t)((j + 2) * 32 + ld_k) * 4096 + hw0 + ld_c + 32];
        }

        const uint32_t bbase = sb + OFF_B + (uint32_t)(j & 1) * B_BUF;
#pragma unroll
        for (int step = 0; step < 2; ++step) {
            uint32_t brow = (uint32_t)(step * 16 + (lid & 15));
            uint32_t Bf[2][4];
#pragma unroll
            for (int bh = 0; bh < 2; ++bh) {
                uint32_t bcol = (uint32_t)(warp_n * 32 + bh * 16 + ((lid >> 4) << 3));
                ldsm_x4_t(Bf[bh], bbase + brow * B_PITCH + bcol * 2);
            }
#pragma unroll
            for (int mt = 0; mt < 4; ++mt) {
                int sbase = ((warp_m * 64 + mt * 16) - j * 32) & 255;
                uint32_t arow = (uint32_t)(sbase + (lid & 15));
                uint32_t acol = (uint32_t)(step * 32 + ((lid >> 4) << 4));  // bytes
                uint32_t Af[4];
                ldsm_x4(Af, sb + OFF_A + arow * A_PITCH + acol);
                mma16816(acc[mt][0], Af, Bf[0]);
                mma16816(acc[mt][1], Af, Bf[0] + 2);
                mma16816(acc[mt][2], Af, Bf[1]);
                mma16816(acc[mt][3], Af, Bf[1] + 2);
            }
        }

        if (j < 7) {
            uint32_t nb = OFF_B + (uint32_t)((j + 1) & 1) * B_BUF;
            sts_h(smem, nb + so, vAa);
            sts_h(smem, nb + so + 64, vAb);
            vAa = vBa;
            vAb = vBb;
        }
    }

    // Epilogue: direct stores (lane quads cover 32B sectors)
#pragma unroll
    for (int mt = 0; mt < 4; ++mt) {
        int c = warp_m * 64 + mt * 16 + (lid >> 2);
#pragma unroll
        for (int nq = 0; nq < 4; ++nq) {
            int col = hw0 + warp_n * 32 + nq * 8 + (lid & 3) * 2;
            *(float2*)&outn[(size_t)c * 4096 + col] =
                make_float2(acc[mt][nq][0], acc[mt][nq][1]);
            *(float2*)&outn[(size_t)(c + 8) * 4096 + col] =
                make_float2(acc[mt][nq][2], acc[mt][nq][3]);
        }
    }
}

// ---------------------------------------------------------------------------
extern "C" void kernel_launch(void* const* d_in, const int* in_sizes, int n_in,
                              void* d_out, int out_size) {
    const float* act;
    const float* filt;
    if (n_in >= 2 && in_sizes[0] == 27) {
        filt = (const float*)d_in[0];
        act  = (const float*)d_in[1];
    } else {
        act  = (const float*)d_in[0];
        filt = (const float*)d_in[1];
    }

    cudaFuncSetAttribute(mma_toeplitz_kernel,
                         cudaFuncAttributeMaxDynamicSharedMemorySize, SMEM_BYTES);

    prep_kernel<<<1, 256>>>(filt);

    dim3 grid(4096 / 64, 32);   // (64, 32) = 2048 CTAs
    mma_toeplitz_kernel<<<grid, 256, SMEM_BYTES>>>(act, (float*)d_out);
}